// round 17
// baseline (speedup 1.0000x reference)
#include <cuda_runtime.h>
#include <cuda_bf16.h>
#include <cstdint>

#define BB 256
#define SS 2048
#define KK 64
#define PF 8      // score prefetch depth (steps)
#define HALF 1024 // steps per half-chain
#define FULLM 0xffffffffu

// Scratch (no allocations allowed in kernel_launch)
// g_Mpack[dir][j][p]: bf16x2 pair for state j, input pair p.
//   dir 0 (fwd): (M[2p][j], M[2p+1][j])  — column j
//   dir 1 (bwd): (M[j][2p], M[j][2p+1])  — row j
__device__ uint32_t g_Mpack[2][KK][32];
__device__ float  g_Af[BB * KK];
__device__ float  g_Bb[BB * KK];
__device__ int    g_cf[BB];
__device__ int    g_cb[BB];
__device__ double g_logZ[BB];
__device__ double g_gold[BB];

static __device__ __forceinline__ float warp_sum(float v) {
#pragma unroll
    for (int o = 16; o > 0; o >>= 1)
        v += __shfl_xor_sync(FULLM, v, o);
    return v;
}
static __device__ __forceinline__ __nv_bfloat162 asbf2(uint32_t u) {
    __nv_bfloat162 h;
    *(uint32_t*)&h = u;
    return h;
}

// Dual-column 64-wide matvec; W exchanged via warp shuffles (no SMEM).
// Returns (sum for j0, sum for j0+1) in f32.
static __device__ __forceinline__ float2 mv64_shfl(uint32_t W,
                                                   const uint32_t (&Mr)[64]) {
    __nv_bfloat162 z = __floats2bfloat162_rn(0.f, 0.f);
    __nv_bfloat162 ax0 = z, ax1 = z, ax2 = z, ax3 = z;
    __nv_bfloat162 ay0 = z, ay1 = z, ay2 = z, ay3 = z;
#pragma unroll
    for (int p = 0; p < 32; p += 4) {
        uint32_t wa = __shfl_sync(FULLM, W, p + 0);
        uint32_t wb = __shfl_sync(FULLM, W, p + 1);
        uint32_t wc = __shfl_sync(FULLM, W, p + 2);
        uint32_t wd = __shfl_sync(FULLM, W, p + 3);
        ax0 = __hfma2(asbf2(wa), asbf2(Mr[p + 0]), ax0);
        ay0 = __hfma2(asbf2(wa), asbf2(Mr[32 + p + 0]), ay0);
        ax1 = __hfma2(asbf2(wb), asbf2(Mr[p + 1]), ax1);
        ay1 = __hfma2(asbf2(wb), asbf2(Mr[32 + p + 1]), ay1);
        ax2 = __hfma2(asbf2(wc), asbf2(Mr[p + 2]), ax2);
        ay2 = __hfma2(asbf2(wc), asbf2(Mr[32 + p + 2]), ay2);
        ax3 = __hfma2(asbf2(wd), asbf2(Mr[p + 3]), ax3);
        ay3 = __hfma2(asbf2(wd), asbf2(Mr[32 + p + 3]), ay3);
    }
    float2 f0 = __bfloat1622float2(ax0), f1 = __bfloat1622float2(ax1);
    float2 f2 = __bfloat1622float2(ax2), f3 = __bfloat1622float2(ax3);
    float sx = (f0.x + f0.y) + (f1.x + f1.y) + (f2.x + f2.y) + (f3.x + f3.y);
    f0 = __bfloat1622float2(ay0); f1 = __bfloat1622float2(ay1);
    f2 = __bfloat1622float2(ay2); f3 = __bfloat1622float2(ay3);
    float sy = (f0.x + f0.y) + (f1.x + f1.y) + (f2.x + f2.y) + (f3.x + f3.y);
    return make_float2(sx, sy);
}

// ---------- kernels ----------
__global__ void init_kernel(const float* __restrict__ T) {
    int i = blockIdx.x * blockDim.x + threadIdx.x;
    if (i >= 2 * KK * 32) return;
    int dir = i >> 11, j = (i >> 5) & 63, p = i & 31;
    float a, b;
    if (dir == 0) { a = expf(T[(2 * p) * KK + j]); b = expf(T[(2 * p + 1) * KK + j]); }
    else          { a = expf(T[j * KK + 2 * p]);   b = expf(T[j * KK + 2 * p + 1]); }
    __nv_bfloat162 h = __floats2bfloat162_rn(a, b);
    g_Mpack[dir][j][p] = *(uint32_t*)&h;
}

// 128 CTAs x 128 threads = 512 fully independent warps, one half-chain each:
// warp 0 = fwd batch 2b, warp 1 = fwd 2b+1, warp 2 = bwd 2b, warp 3 = bwd 2b+1.
// Wavefront lives in REGISTERS (bf16x2/thread), exchanged via shuffles.
// The loop has NO shared memory, NO barriers, NO syncwarp.
__global__ void __launch_bounds__(128, 1) main_kernel(
    const float* __restrict__ scores,
    const float* __restrict__ source,
    const float* __restrict__ sink) {
    const int tid = threadIdx.x, wid = tid >> 5, lane = tid & 31;
    const bool fwd = (wid < 2);
    const int b = (blockIdx.x << 1) + (wid & 1);
    const int j0 = 2 * lane;
    const float* sc = scores + (size_t)b * (SS * KK);
    const float LOG2E = 1.44269504088896340736f;

    // M slices for my two states (bf16x2, 64 regs).
    uint32_t Mr[64];
    {
        const uint32_t* m0 = &g_Mpack[fwd ? 0 : 1][j0][0];
        const uint32_t* m1 = &g_Mpack[fwd ? 0 : 1][j0 + 1][0];
#pragma unroll
        for (int p = 0; p < 32; ++p) { Mr[p] = m0[p]; Mr[32 + p] = m1[p]; }
    }

    const int t0  = fwd ? 0 : SS - 1;
    const int sgn = fwd ? 1 : -1;
    const ptrdiff_t pstep = (ptrdiff_t)sgn * KK;

    // Score prefetch ring (float2: states j0, j0+1) + rolling pointer.
    float2 ring[PF];
#pragma unroll
    for (int k = 0; k < PF; ++k)
        ring[k] = __ldg((const float2*)&sc[(size_t)(t0 + sgn * (1 + k)) * KK + j0]);
    const float* pp = &sc[(size_t)(t0 + sgn * (1 + PF)) * KK + j0];

    // Init: fwd W_0 = exp(source + s_0); bwd = exp(sink + s_{2047}).
    uint32_t W;
    {
        float2 bnd = fwd ? __ldg((const float2*)&source[j0])
                         : __ldg((const float2*)&sink[j0]);
        float2 s0 = __ldg((const float2*)&sc[(size_t)t0 * KK + j0]);
        float w0 = exp2f((bnd.x + s0.x) * LOG2E);
        float w1 = exp2f((bnd.y + s0.y) * LOG2E);
        __nv_bfloat162 h = __floats2bfloat162_rn(w0, w1);
        W = *(uint32_t*)&h;
    }
    int c = 0;
    float o0 = 0.f, o1 = 0.f;   // live-out scaled f32 wavefront

#pragma unroll 1
    for (int base = 1; base < HALF; base += PF) {
#pragma unroll
        for (int k = 0; k < PF; ++k) {
            const int v = base + k;
            if (v >= HALF) break;          // v = 1..HALF-1 exactly

            // Consistent power-of-2 rescale from bf16 exponent of A[0]
            // (lane 0's low half, broadcast by shuffle -> bit-identical).
            uint32_t head = __shfl_sync(FULLM, W, 0);
            int e0 = (int)((head >> 7) & 0xFF);
            float scale = __uint_as_float((uint32_t)(254 - e0) << 23);
            c += e0 - 127;

            float2 sv = ring[k];
            ring[k] = __ldg((const float2*)pp);
            pp += pstep;

            float2 s = mv64_shfl(W, Mr);
            float es0 = exp2f(sv.x * LOG2E);
            float es1 = exp2f(sv.y * LOG2E);
            o0 = s.x * (es0 * scale);
            o1 = s.y * (es1 * scale);
            __nv_bfloat162 h = __floats2bfloat162_rn(o0, o1);
            W = *(uint32_t*)&h;
        }
    }

    if (fwd) {
        g_Af[(size_t)b * KK + j0]     = o0;   // alpha_{1023} (scaled), f32
        g_Af[(size_t)b * KK + j0 + 1] = o1;
        if (lane == 0) g_cf[b] = c;
    } else {
        // beta'_{1023} = M * Bv_{1024} (no es), one extra renormalized matvec.
        uint32_t head = __shfl_sync(FULLM, W, 0);
        int e0 = (int)((head >> 7) & 0xFF);
        float scale = __uint_as_float((uint32_t)(254 - e0) << 23);
        c += e0 - 127;
        float2 s = mv64_shfl(W, Mr);
        g_Bb[(size_t)b * KK + j0]     = s.x * scale;
        g_Bb[(size_t)b * KK + j0 + 1] = s.y * scale;
        if (lane == 0) g_cb[b] = c;
    }
}

// logZ_b = log(sum_j Af[b][j]*Bb[b][j]) + (cf+cb)*ln2
__global__ __launch_bounds__(64) void combine_kernel() {
    __shared__ float sRed[2];
    const int b = blockIdx.x, j = threadIdx.x;
    float v = g_Af[b * KK + j] * g_Bb[b * KK + j];
    float ws = warp_sum(v);
    if ((j & 31) == 0) sRed[j >> 5] = ws;
    __syncthreads();
    if (j == 0) {
        float tot = sRed[0] + sRed[1];
        g_logZ[b] = ((double)log2f(tot) + (double)(g_cf[b] + g_cb[b])) *
                    0.69314718055994530942;
    }
}

__global__ __launch_bounds__(256) void gold_kernel(
    const float* __restrict__ scores,
    const int* __restrict__ states,
    const float* __restrict__ T,
    const float* __restrict__ source,
    const float* __restrict__ sink) {
    __shared__ float red[256];
    const int b = blockIdx.x, tid = threadIdx.x;
    const int*   st = states + (size_t)b * SS;
    const float* sc = scores + (size_t)b * (SS * KK);

    float acc = 0.f;
    for (int t = tid; t < SS; t += 256) {
        int s0 = __ldg(&st[t]);
        acc += __ldg(&sc[t * KK + s0]);
        if (t + 1 < SS) acc += __ldg(&T[s0 * KK + __ldg(&st[t + 1])]);
    }
    red[tid] = acc;
    __syncthreads();
#pragma unroll
    for (int off = 128; off > 0; off >>= 1) {
        if (tid < off) red[tid] += red[tid + off];
        __syncthreads();
    }
    if (tid == 0)
        g_gold[b] = (double)red[0] + (double)__ldg(&source[__ldg(&st[0])]) +
                    (double)__ldg(&sink[__ldg(&st[SS - 1])]);
}

__global__ __launch_bounds__(256) void finalize_kernel(float* __restrict__ out) {
    __shared__ double red[256];
    const int tid = threadIdx.x;
    red[tid] = g_logZ[tid] - g_gold[tid];
    __syncthreads();
#pragma unroll
    for (int off = 128; off > 0; off >>= 1) {
        if (tid < off) red[tid] += red[tid + off];
        __syncthreads();
    }
    if (tid == 0) *out = (float)(red[0] * (1.0 / BB));
}

extern "C" void kernel_launch(void* const* d_in, const int* in_sizes, int n_in,
                              void* d_out, int out_size) {
    const float* scores = (const float*)d_in[0];   // [B,S,K] f32
    const int*   states = (const int*)d_in[1];     // [B,S] i32
    const float* T      = (const float*)d_in[2];   // [K,K] f32
    const float* source = (const float*)d_in[3];   // [K] f32
    const float* sink   = (const float*)d_in[4];   // [K] f32
    float* out = (float*)d_out;

    init_kernel<<<16, 256>>>(T);
    main_kernel<<<BB / 2, 128>>>(scores, source, sink);
    gold_kernel<<<BB, 256>>>(scores, states, T, source, sink);
    combine_kernel<<<BB, 64>>>();
    finalize_kernel<<<1, 256>>>(out);
}